// round 2
// baseline (speedup 1.0000x reference)
#include <cuda_runtime.h>
#include <cuda_bf16.h>
#include <cstdint>

// ---------------- problem constants ----------------
#define BATCH   2
#define NSEQ    1024
#define DIMF    512
#define HEADS   8
#define DKH     64
#define BH      16              // BATCH*HEADS
#define NN      1048576ull      // NSEQ*NSEQ
#define ND      65536ull        // NSEQ*DKH
#define NN16    16777216ull     // BH*NN

// ---------------- scratch pool (static device memory; allocation-free) -----
#define OFF_Q0  0ull
#define OFF_K0  1048576ull
#define OFF_V0  2097152ull
#define OFF_Q1  3145728ull
#define OFF_K1  4194304ull
#define OFF_V1  5242880ull
#define OFF_S0  6291456ull
#define OFF_S1  (OFF_S0 + NN16)
#define OFF_A0  (OFF_S1 + NN16)
#define OFF_A1  (OFF_A0 + NN16)
#define OFF_CF  (OFF_A1 + NN16)
#define OFF_CB  (OFF_CF + NN16)
#define OFF_TMP (OFF_CB + NN16)
#define OFF_YCH (OFF_TMP + 1048576ull)
#define OFF_YB  (OFF_YCH + 1048576ull)
#define OFF_Y   (OFF_YB  + 1048576ull)
#define OFF_SCR (OFF_Y   + 1048576ull)
#define POOL_TOTAL (OFF_SCR + 6291456ull)   // 117,440,512 floats = 470 MB

#define OFF_A0H 0ull
#define OFF_A1H NN16

static __device__ float         g_pool [POOL_TOTAL];
static __device__ __nv_bfloat16 g_poolh[2ull * NN16];

// ---------------- helpers ----------------
__device__ __forceinline__ float tanh_fast(float x) {
    float y;
    asm("tanh.approx.f32 %0, %1;" : "=f"(y) : "f"(x));
    return y;
}

// =====================================================================
// Generic fp32 SIMT GEMM: C = alpha * A @ B (or A @ B^T), batched.
// BM=BN=64, BK=16, 256 threads, 4x4 microtile. All dims multiples of 64/16.
// Null ext pointer => use pool + offset.
// =====================================================================
template<bool TRANSB>
__global__ __launch_bounds__(256) void gemm_f32(
    const float* __restrict__ Aext, size_t offA,
    const float* __restrict__ Bext, size_t offB,
    float* __restrict__ Cext, size_t offC,
    int lda, int ldb, int ldc,
    long long sA, long long sB, long long sC,
    int K, float alpha)
{
    const float* A = Aext ? Aext : (g_pool + offA);
    const float* B = Bext ? Bext : (g_pool + offB);
    float*       C = Cext ? Cext : (g_pool + offC);
    int z = blockIdx.z;
    A += (size_t)z * (size_t)sA;
    B += (size_t)z * (size_t)sB;
    C += (size_t)z * (size_t)sC;

    __shared__ float As[16][65];
    __shared__ float Bs[16][65];

    int tid = threadIdx.x;
    int tx = tid & 15, ty = tid >> 4;
    int bm = blockIdx.y * 64, bn = blockIdx.x * 64;

    float acc[4][4] = {};

    for (int k0 = 0; k0 < K; k0 += 16) {
        #pragma unroll
        for (int i = 0; i < 4; i++) {
            int idx = i * 256 + tid;
            int r = idx >> 4, c = idx & 15;
            As[c][r] = A[(size_t)(bm + r) * lda + k0 + c];
        }
        if (TRANSB) {
            #pragma unroll
            for (int i = 0; i < 4; i++) {
                int idx = i * 256 + tid;
                int r = idx >> 4, c = idx & 15;
                Bs[c][r] = B[(size_t)(bn + r) * ldb + k0 + c];
            }
        } else {
            #pragma unroll
            for (int i = 0; i < 4; i++) {
                int idx = i * 256 + tid;
                int r = idx >> 6, c = idx & 63;
                Bs[r][c] = B[(size_t)(k0 + r) * ldb + bn + c];
            }
        }
        __syncthreads();
        #pragma unroll
        for (int kk = 0; kk < 16; kk++) {
            float a[4], b[4];
            #pragma unroll
            for (int i = 0; i < 4; i++) a[i] = As[kk][ty * 4 + i];
            #pragma unroll
            for (int j = 0; j < 4; j++) b[j] = Bs[kk][tx * 4 + j];
            #pragma unroll
            for (int i = 0; i < 4; i++)
                #pragma unroll
                for (int j = 0; j < 4; j++)
                    acc[i][j] += a[i] * b[j];
        }
        __syncthreads();
    }
    #pragma unroll
    for (int i = 0; i < 4; i++)
        #pragma unroll
        for (int j = 0; j < 4; j++)
            C[(size_t)(bm + ty * 4 + i) * ldc + bn + tx * 4 + j] = alpha * acc[i][j];
}

// =====================================================================
// Scatter x@Wqkv result into q/k/v [BH][N][DK] layouts
// scratch layout: [w(2)][m(2048)][j(1536)], j -> (s, h, d)
// =====================================================================
__global__ void scatter_qkv() {
    int idx = blockIdx.x * 256 + threadIdx.x;   // 0 .. 2*2048*1536-1
    if (idx >= 2 * 2048 * 1536) return;
    int w   = idx / (2048 * 1536);
    int rem = idx - w * (2048 * 1536);
    int m = rem / 1536;
    int j = rem - m * 1536;
    int b = m >> 10, tok = m & 1023;
    int s = j >> 9;
    int h = (j >> 6) & 7;
    int d = j & 63;
    float val = g_pool[OFF_SCR + (size_t)idx];
    size_t baseoff;
    if (w == 0) baseoff = (s == 0) ? OFF_Q0 : (s == 1) ? OFF_K0 : OFF_V0;
    else        baseoff = (s == 0) ? OFF_Q1 : (s == 1) ? OFF_K1 : OFF_V1;
    g_pool[baseoff + ((size_t)(b * 8 + h) * NSEQ + tok) * DKH + d] = val;
}

// =====================================================================
// Row softmax over 1024 elems; optionally also write bf16 copy.
// grid = 16384 rows, 256 threads.
// =====================================================================
template<int WB>
__global__ __launch_bounds__(256) void softmax_rows(size_t inOff, size_t outOff, size_t bfOff)
{
    const float* S = g_pool + inOff;
    float*       A = g_pool + outOff;
    size_t base = (size_t)blockIdx.x * 1024;
    int tid = threadIdx.x;
    int warp = tid >> 5, lane = tid & 31;

    float v[4];
    #pragma unroll
    for (int i = 0; i < 4; i++) v[i] = S[base + tid + i * 256];
    float mx = fmaxf(fmaxf(v[0], v[1]), fmaxf(v[2], v[3]));
    #pragma unroll
    for (int o = 16; o > 0; o >>= 1) mx = fmaxf(mx, __shfl_xor_sync(0xffffffffu, mx, o));
    __shared__ float red[8];
    if (lane == 0) red[warp] = mx;
    __syncthreads();
    float mAll = red[0];
    #pragma unroll
    for (int w = 1; w < 8; w++) mAll = fmaxf(mAll, red[w]);
    __syncthreads();

    float e[4], s = 0.f;
    #pragma unroll
    for (int i = 0; i < 4; i++) { e[i] = __expf(v[i] - mAll); s += e[i]; }
    #pragma unroll
    for (int o = 16; o > 0; o >>= 1) s += __shfl_xor_sync(0xffffffffu, s, o);
    if (lane == 0) red[warp] = s;
    __syncthreads();
    float tot = 0.f;
    #pragma unroll
    for (int w = 0; w < 8; w++) tot += red[w];
    float inv = __fdividef(1.0f, tot);
    #pragma unroll
    for (int i = 0; i < 4; i++) {
        float p = e[i] * inv;
        A[base + tid + i * 256] = p;
        if (WB) g_poolh[bfOff + base + tid + i * 256] = __float2bfloat16(p);
    }
}

// =====================================================================
// Batched bf16 mma GEMM for C_fwd / C_bwd (32 batches of 1024^3, NN).
// z<16: Cf[z] = A0h[z] @ A1h[z];  z>=16: Cb[z-16] = A1h[z-16] @ A0h[z-16].
// CTA tile 128x128x32, 8 warps (2x4), warp tile 64x32, mma m16n8k16.
// =====================================================================
__device__ __forceinline__ void mma16816(float* c, const uint32_t* a, const uint32_t* b) {
    asm volatile(
        "mma.sync.aligned.m16n8k16.row.col.f32.bf16.bf16.f32 "
        "{%0,%1,%2,%3}, {%4,%5,%6,%7}, {%8,%9}, {%0,%1,%2,%3};"
        : "+f"(c[0]), "+f"(c[1]), "+f"(c[2]), "+f"(c[3])
        : "r"(a[0]), "r"(a[1]), "r"(a[2]), "r"(a[3]), "r"(b[0]), "r"(b[1]));
}

__global__ __launch_bounds__(256) void gemm_chain_bf16() {
    int z = blockIdx.z;
    const __nv_bfloat16 *A, *B;
    float* C;
    if (z < 16) {
        A = g_poolh + OFF_A0H + (size_t)z * NN;
        B = g_poolh + OFF_A1H + (size_t)z * NN;
        C = g_pool  + OFF_CF  + (size_t)z * NN;
    } else {
        int zz = z - 16;
        A = g_poolh + OFF_A1H + (size_t)zz * NN;
        B = g_poolh + OFF_A0H + (size_t)zz * NN;
        C = g_pool  + OFF_CB  + (size_t)zz * NN;
    }
    __shared__ __nv_bfloat16 As[128][40];   // padded: conflict-free frag loads
    __shared__ __nv_bfloat16 Bt[128][40];   // B stored transposed [n][k]

    int tid = threadIdx.x, warp = tid >> 5, lane = tid & 31;
    int bm = blockIdx.y * 128, bn = blockIdx.x * 128;
    int wm = (warp >> 2) * 64, wn = (warp & 3) * 32;

    float acc[4][4][4] = {};

    for (int k0 = 0; k0 < 1024; k0 += 32) {
        #pragma unroll
        for (int i = 0; i < 8; i++) {
            int idx = i * 256 + tid;
            int r = idx >> 4, cp = idx & 15;
            *(__nv_bfloat162*)&As[r][cp * 2] =
                *(const __nv_bfloat162*)&A[(size_t)(bm + r) * 1024 + k0 + cp * 2];
        }
        #pragma unroll
        for (int i = 0; i < 8; i++) {
            int idx = i * 256 + tid;
            int n = idx & 127, kp = idx >> 7;
            __nv_bfloat162 p;
            p.x = B[(size_t)(k0 + kp * 2)     * 1024 + bn + n];
            p.y = B[(size_t)(k0 + kp * 2 + 1) * 1024 + bn + n];
            *(__nv_bfloat162*)&Bt[n][kp * 2] = p;
        }
        __syncthreads();
        #pragma unroll
        for (int ks = 0; ks < 2; ks++) {
            int kc  = ks * 16 + (lane & 3) * 2;
            int grp = lane >> 2;
            uint32_t a[4][4], b[4][2];
            #pragma unroll
            for (int mt = 0; mt < 4; mt++) {
                int r = wm + mt * 16 + grp;
                a[mt][0] = *(const uint32_t*)&As[r][kc];
                a[mt][1] = *(const uint32_t*)&As[r + 8][kc];
                a[mt][2] = *(const uint32_t*)&As[r][kc + 8];
                a[mt][3] = *(const uint32_t*)&As[r + 8][kc + 8];
            }
            #pragma unroll
            for (int nt = 0; nt < 4; nt++) {
                int n = wn + nt * 8 + grp;
                b[nt][0] = *(const uint32_t*)&Bt[n][kc];
                b[nt][1] = *(const uint32_t*)&Bt[n][kc + 8];
            }
            #pragma unroll
            for (int mt = 0; mt < 4; mt++)
                #pragma unroll
                for (int nt = 0; nt < 4; nt++)
                    mma16816(acc[mt][nt], a[mt], b[nt]);
        }
        __syncthreads();
    }
    #pragma unroll
    for (int mt = 0; mt < 4; mt++) {
        #pragma unroll
        for (int nt = 0; nt < 4; nt++) {
            int r = bm + wm + mt * 16 + (lane >> 2);
            int c = bn + wn + nt * 8 + (lane & 3) * 2;
            *(float2*)&C[(size_t)r * 1024 + c]       = make_float2(acc[mt][nt][0], acc[mt][nt][1]);
            *(float2*)&C[(size_t)(r + 8) * 1024 + c] = make_float2(acc[mt][nt][2], acc[mt][nt][3]);
        }
    }
}

// =====================================================================
// Fused: feat(6ch incl. transposes + logs) -> conv1+gelu -> conv2+sigmoid
//        -> gates -> Smix.  Smix written in-place into Cb buffer.
// grid (32 n-tiles, 32 m-tiles, 16 bh), 256 threads (32x, 8y; 4 rows each).
// =====================================================================
__global__ __launch_bounds__(256) void fuse_kernel(
    const float* __restrict__ w1, const float* __restrict__ b1,
    const float* __restrict__ w2, const float* __restrict__ b2)
{
    __shared__ float s0t[32][33], s1t[32][33];
    __shared__ float w1s[16][6], b1s[16], w2s[4][16], b2s[4];

    size_t off = (size_t)blockIdx.z * NN;
    int m0 = blockIdx.y * 32, n0 = blockIdx.x * 32;
    int tid = threadIdx.x;
    int tx = tid & 31, ty = tid >> 5;

    if (tid < 96)       ((float*)w1s)[tid]        = w1[tid];
    else if (tid < 112) b1s[tid - 96]             = b1[tid - 96];
    else if (tid < 176) ((float*)w2s)[tid - 112]  = w2[tid - 112];
    else if (tid < 180) b2s[tid - 176]            = b2[tid - 176];

    const float* S0 = g_pool + OFF_S0;
    const float* S1 = g_pool + OFF_S1;
    const float* Cf = g_pool + OFF_CF;
    float*       Cb = g_pool + OFF_CB;   // read Cb, write Smix (same index)

    #pragma unroll
    for (int r = 0; r < 4; r++) {
        int rr = ty + r * 8;
        s0t[rr][tx] = S0[off + (size_t)(n0 + rr) * 1024 + m0 + tx];
        s1t[rr][tx] = S1[off + (size_t)(n0 + rr) * 1024 + m0 + tx];
    }
    __syncthreads();

    #pragma unroll
    for (int r = 0; r < 4; r++) {
        int row = ty + r * 8;
        size_t gidx = off + (size_t)(m0 + row) * 1024 + n0 + tx;
        float s0 = S0[gidx], s1 = S1[gidx];
        float f2 = s0t[tx][row];   // S0^T
        float f3 = s1t[tx][row];   // S1^T
        float cr = __logf(Cf[gidx] + 1e-6f);
        float cl = __logf(Cb[gidx] + 1e-6f);
        float f[6] = { s0, s1, f2, f3, cr, cl };

        float g[4];
        #pragma unroll
        for (int o = 0; o < 4; o++) g[o] = b2s[o];

        #pragma unroll
        for (int oh = 0; oh < 16; oh++) {
            float a = b1s[oh];
            #pragma unroll
            for (int c = 0; c < 6; c++) a += w1s[oh][c] * f[c];
            float gx = 0.7978845608028654f * (a + 0.044715f * a * a * a);
            float hg = 0.5f * a * (1.0f + tanh_fast(gx));
            #pragma unroll
            for (int o = 0; o < 4; o++) g[o] += w2s[o][oh] * hg;
        }
        #pragma unroll
        for (int o = 0; o < 4; o++) g[o] = __fdividef(1.0f, 1.0f + __expf(-g[o]));

        float d   = fabsf(s0 - s1);
        float lse = fmaxf(s0, s1) + __logf(1.0f + __expf(-d));
        float smix = s0 + g[0] * s1 + g[1] * (lse - s0) - g[2] * (0.5f * s1) + g[3] * cr;
        Cb[gidx] = smix;
    }
}

// =====================================================================
// Combine: Y[b][tok][h*64+d] = yb[bh][tok][d] + sigmoid(cvl) * ych[bh][tok][d]
// =====================================================================
__global__ void combine_kernel(const float* __restrict__ cvl) {
    int idx = blockIdx.x * 256 + threadIdx.x;    // 0 .. 16*1024*64-1
    if (idx >= (int)(BH * ND)) return;
    int bh  = idx >> 16;
    int rr  = idx & 65535;
    int tok = rr >> 6;
    int d   = rr & 63;
    int b = bh >> 3, h = bh & 7;
    float sig = __fdividef(1.0f, 1.0f + __expf(-cvl[0]));
    float y = g_pool[OFF_YB + (size_t)idx] + sig * g_pool[OFF_YCH + (size_t)idx];
    g_pool[OFF_Y + ((size_t)(b * 1024 + tok)) * 512 + h * 64 + d] = y;
}

// =====================================================================
// Host launch sequence
// =====================================================================
extern "C" void kernel_launch(void* const* d_in, const int* in_sizes, int n_in,
                              void* d_out, int out_size)
{
    const float* x     = (const float*)d_in[0];
    const float* Wqkv0 = (const float*)d_in[1];
    const float* Wqkv1 = (const float*)d_in[2];
    const float* Wproj = (const float*)d_in[3];
    const float* c1w   = (const float*)d_in[4];
    const float* c1b   = (const float*)d_in[5];
    const float* c2w   = (const float*)d_in[6];
    const float* c2b   = (const float*)d_in[7];
    const float* cvl   = (const float*)d_in[8];
    float* out = (float*)d_out;

    // 1) qkv GEMMs: x[2048,512] @ Wqkv{0,1}[512,1536] -> scratch
    gemm_f32<false><<<dim3(24, 32, 1), 256>>>(x, 0, Wqkv0, 0, nullptr, OFF_SCR,
        512, 1536, 1536, 0, 0, 0, 512, 1.0f);
    gemm_f32<false><<<dim3(24, 32, 1), 256>>>(x, 0, Wqkv1, 0, nullptr, OFF_SCR + 3145728ull,
        512, 1536, 1536, 0, 0, 0, 512, 1.0f);

    // 2) scatter into q/k/v [BH][N][DK]
    scatter_qkv<<<(2 * 2048 * 1536 + 255) / 256, 256>>>();

    // 3) S0 = q0 k0^T * 1/8 ; S1 = q1 k1^T * 1/8   (batched NT, 16)
    gemm_f32<true><<<dim3(16, 16, 16), 256>>>(nullptr, OFF_Q0, nullptr, OFF_K0, nullptr, OFF_S0,
        64, 64, 1024, (long long)ND, (long long)ND, (long long)NN, 64, 0.125f);
    gemm_f32<true><<<dim3(16, 16, 16), 256>>>(nullptr, OFF_Q1, nullptr, OFF_K1, nullptr, OFF_S1,
        64, 64, 1024, (long long)ND, (long long)ND, (long long)NN, 64, 0.125f);

    // 4) A0 = softmax(S0) (+bf16) ; A1 = softmax(S1) (+bf16)
    softmax_rows<1><<<16384, 256>>>(OFF_S0, OFF_A0, OFF_A0H);
    softmax_rows<1><<<16384, 256>>>(OFF_S1, OFF_A1, OFF_A1H);

    // 5) C_fwd = A0@A1, C_bwd = A1@A0  (bf16 mma, fp32 accum; 32 batches)
    gemm_chain_bf16<<<dim3(8, 8, 32), 256>>>();

    // 6) fused feat/conv/gates/Smix  (Smix -> Cb buffer in place)
    fuse_kernel<<<dim3(32, 32, 16), 256>>>(c1w, c1b, c2w, c2b);

    // 7) A = softmax(Smix) -> reuse S0 buffer
    softmax_rows<0><<<16384, 256>>>(OFF_CB, OFF_S0, 0);

    // 8) tmp = A1 @ v1 ; ych = A0 @ tmp ; yb = A @ v0   (batched NN, 16)
    gemm_f32<false><<<dim3(1, 16, 16), 256>>>(nullptr, OFF_A1, nullptr, OFF_V1, nullptr, OFF_TMP,
        1024, 64, 64, (long long)NN, (long long)ND, (long long)ND, 1024, 1.0f);
    gemm_f32<false><<<dim3(1, 16, 16), 256>>>(nullptr, OFF_A0, nullptr, OFF_TMP, nullptr, OFF_YCH,
        1024, 64, 64, (long long)NN, (long long)ND, (long long)ND, 1024, 1.0f);
    gemm_f32<false><<<dim3(1, 16, 16), 256>>>(nullptr, OFF_S0, nullptr, OFF_V0, nullptr, OFF_YB,
        1024, 64, 64, (long long)NN, (long long)ND, (long long)ND, 1024, 1.0f);

    // 9) combine into Y[2048][512]
    combine_kernel<<<(BH * ND + 255) / 256, 256>>>(cvl);

    // 10) out = Y @ Wproj  [2048,512] @ [512,512]
    gemm_f32<false><<<dim3(8, 32, 1), 256>>>(nullptr, OFF_Y, Wproj, 0, out, 0,
        512, 512, 512, 0, 0, 0, 512, 1.0f);

    (void)in_sizes; (void)n_in; (void)out_size;
}

// round 3
// speedup vs baseline: 1.2916x; 1.2916x over previous
#include <cuda_runtime.h>
#include <cuda_bf16.h>
#include <cstdint>

// ---------------- problem constants ----------------
#define BATCH   2
#define NSEQ    1024
#define DIMF    512
#define HEADS   8
#define DKH     64
#define BH      16              // BATCH*HEADS
#define NN      1048576ull      // NSEQ*NSEQ
#define ND      65536ull        // NSEQ*DKH
#define NN16    16777216ull     // BH*NN

// ---------------- scratch pool (static device memory; allocation-free) -----
#define OFF_Q0  0ull
#define OFF_K0  1048576ull
#define OFF_V0  2097152ull
#define OFF_Q1  3145728ull
#define OFF_K1  4194304ull
#define OFF_V1  5242880ull
#define OFF_S0  6291456ull
#define OFF_S1  (OFF_S0 + NN16)
#define OFF_A0  (OFF_S1 + NN16)
#define OFF_A1  (OFF_A0 + NN16)
#define OFF_CF  (OFF_A1 + NN16)
#define OFF_CB  (OFF_CF + NN16)
#define OFF_TMP (OFF_CB + NN16)
#define OFF_YCH (OFF_TMP + 1048576ull)
#define OFF_YB  (OFF_YCH + 1048576ull)
#define OFF_Y   (OFF_YB  + 1048576ull)
#define OFF_SCR (OFF_Y   + 1048576ull)
#define POOL_TOTAL (OFF_SCR + 6291456ull)   // 117,440,512 floats = 470 MB

#define OFF_A0H 0ull
#define OFF_A1H NN16

static __device__ float         g_pool [POOL_TOTAL];
static __device__ __nv_bfloat16 g_poolh[2ull * NN16];

// ---------------- helpers ----------------
__device__ __forceinline__ float tanh_fast(float x) {
    float y;
    asm("tanh.approx.f32 %0, %1;" : "=f"(y) : "f"(x));
    return y;
}

__device__ __forceinline__ uint32_t f2tf32(float x) {
    uint32_t u;
    asm("cvt.rna.tf32.f32 %0, %1;" : "=r"(u) : "f"(x));
    return u;
}

__device__ __forceinline__ void mma_tf32(float* c, const uint32_t* a, const uint32_t* b) {
    asm volatile(
        "mma.sync.aligned.m16n8k8.row.col.f32.tf32.tf32.f32 "
        "{%0,%1,%2,%3}, {%4,%5,%6,%7}, {%8,%9}, {%0,%1,%2,%3};"
        : "+f"(c[0]), "+f"(c[1]), "+f"(c[2]), "+f"(c[3])
        : "r"(a[0]), "r"(a[1]), "r"(a[2]), "r"(a[3]), "r"(b[0]), "r"(b[1]));
}

// =====================================================================
// tf32 tensor-core GEMM: C = alpha * A @ B (or A @ B^T), batched.
// CTA tile 128 x BN, BK=32, 256 threads (8 warps).
// Smem row-stride 36 words => fragment loads are bank-conflict-free.
// Null ext pointer => use pool + offset.
// =====================================================================
template<int BN, int WARPS_M, int WARPS_N, bool TRANSB>
__global__ __launch_bounds__(256) void gemm_tf32(
    const float* __restrict__ Aext, size_t offA,
    const float* __restrict__ Bext, size_t offB,
    float* __restrict__ Cext, size_t offC,
    int lda, int ldb, int ldc,
    long long sA, long long sB, long long sC,
    int K, float alpha)
{
    constexpr int BM = 128, BK = 32, LDS = BK + 4;     // stride 36
    constexpr int WM = BM / WARPS_M;
    constexpr int WN = BN / WARPS_N;
    constexpr int MT = WM / 16;
    constexpr int NT = WN / 8;
    constexpr int BITERS = BN / 32;

    const float* A = Aext ? Aext : (g_pool + offA);
    const float* B = Bext ? Bext : (g_pool + offB);
    float*       C = Cext ? Cext : (g_pool + offC);
    int z = blockIdx.z;
    A += (size_t)z * (size_t)sA;
    B += (size_t)z * (size_t)sB;
    C += (size_t)z * (size_t)sC;

    __shared__ uint32_t As[BM][LDS];
    __shared__ uint32_t Bs[BN][LDS];   // stored [n][k]

    int tid  = threadIdx.x;
    int warp = tid >> 5, lane = tid & 31;
    int grp  = lane >> 2, kq = lane & 3;
    int bm = blockIdx.y * BM, bn = blockIdx.x * BN;
    int wm = (warp / WARPS_N) * WM, wn = (warp % WARPS_N) * WN;

    float acc[MT][NT][4] = {};

    for (int k0 = 0; k0 < K; k0 += BK) {
        // ---- load A tile [BM][BK] (row-major, float4 along K) ----
        #pragma unroll
        for (int i = 0; i < 4; i++) {
            int linear = i * 256 + tid;          // over BM*BK/4 = 1024 float4
            int r = linear >> 3, c4 = linear & 7;
            float4 v = *(const float4*)&A[(size_t)(bm + r) * lda + k0 + c4 * 4];
            uint4 u = make_uint4(f2tf32(v.x), f2tf32(v.y), f2tf32(v.z), f2tf32(v.w));
            *(uint4*)&As[r][c4 * 4] = u;
        }
        // ---- load B tile into Bs[n][k] ----
        if (TRANSB) {
            // B global [N][K]: same pattern as A
            #pragma unroll
            for (int i = 0; i < BITERS; i++) {
                int linear = i * 256 + tid;      // over BN*BK/4 float4
                int n = linear >> 3, c4 = linear & 7;
                float4 v = *(const float4*)&B[(size_t)(bn + n) * ldb + k0 + c4 * 4];
                uint4 u = make_uint4(f2tf32(v.x), f2tf32(v.y), f2tf32(v.z), f2tf32(v.w));
                *(uint4*)&Bs[n][c4 * 4] = u;
            }
        } else {
            // B global [K][N]: coalesced float4 along N, transpose into smem
            #pragma unroll
            for (int i = 0; i < BITERS; i++) {
                int linear = i * 256 + tid;      // over BK*BN/4 float4
                int n4 = linear % (BN / 4), k = linear / (BN / 4);
                float4 v = *(const float4*)&B[(size_t)(k0 + k) * ldb + bn + n4 * 4];
                Bs[n4 * 4 + 0][k] = f2tf32(v.x);
                Bs[n4 * 4 + 1][k] = f2tf32(v.y);
                Bs[n4 * 4 + 2][k] = f2tf32(v.z);
                Bs[n4 * 4 + 3][k] = f2tf32(v.w);
            }
        }
        __syncthreads();

        #pragma unroll
        for (int ks = 0; ks < 4; ks++) {
            int kc = ks * 8 + kq;
            uint32_t a[MT][4], b[NT][2];
            #pragma unroll
            for (int mt = 0; mt < MT; mt++) {
                int r = wm + mt * 16 + grp;
                a[mt][0] = As[r][kc];
                a[mt][1] = As[r + 8][kc];
                a[mt][2] = As[r][kc + 4];
                a[mt][3] = As[r + 8][kc + 4];
            }
            #pragma unroll
            for (int nt = 0; nt < NT; nt++) {
                int n = wn + nt * 8 + grp;
                b[nt][0] = Bs[n][kc];
                b[nt][1] = Bs[n][kc + 4];
            }
            #pragma unroll
            for (int mt = 0; mt < MT; mt++)
                #pragma unroll
                for (int nt = 0; nt < NT; nt++)
                    mma_tf32(acc[mt][nt], a[mt], b[nt]);
        }
        __syncthreads();
    }

    // ---- epilogue ----
    #pragma unroll
    for (int mt = 0; mt < MT; mt++) {
        #pragma unroll
        for (int nt = 0; nt < NT; nt++) {
            int r = bm + wm + mt * 16 + grp;
            int c = bn + wn + nt * 8 + kq * 2;
            *(float2*)&C[(size_t)r * ldc + c] =
                make_float2(alpha * acc[mt][nt][0], alpha * acc[mt][nt][1]);
            *(float2*)&C[(size_t)(r + 8) * ldc + c] =
                make_float2(alpha * acc[mt][nt][2], alpha * acc[mt][nt][3]);
        }
    }
}

// =====================================================================
// Scatter x@Wqkv result into q/k/v [BH][N][DK] layouts
// scratch layout: [w(2)][m(2048)][j(1536)], j -> (s, h, d)
// =====================================================================
__global__ void scatter_qkv() {
    int idx = blockIdx.x * 256 + threadIdx.x;   // 0 .. 2*2048*1536-1
    if (idx >= 2 * 2048 * 1536) return;
    int w   = idx / (2048 * 1536);
    int rem = idx - w * (2048 * 1536);
    int m = rem / 1536;
    int j = rem - m * 1536;
    int b = m >> 10, tok = m & 1023;
    int s = j >> 9;
    int h = (j >> 6) & 7;
    int d = j & 63;
    float val = g_pool[OFF_SCR + (size_t)idx];
    size_t baseoff;
    if (w == 0) baseoff = (s == 0) ? OFF_Q0 : (s == 1) ? OFF_K0 : OFF_V0;
    else        baseoff = (s == 0) ? OFF_Q1 : (s == 1) ? OFF_K1 : OFF_V1;
    g_pool[baseoff + ((size_t)(b * 8 + h) * NSEQ + tok) * DKH + d] = val;
}

// =====================================================================
// Row softmax over 1024 elems; optionally also write bf16 copy.
// grid = 16384 rows, 256 threads.
// =====================================================================
template<int WB>
__global__ __launch_bounds__(256) void softmax_rows(size_t inOff, size_t outOff, size_t bfOff)
{
    const float* S = g_pool + inOff;
    float*       A = g_pool + outOff;
    size_t base = (size_t)blockIdx.x * 1024;
    int tid = threadIdx.x;
    int warp = tid >> 5, lane = tid & 31;

    float v[4];
    #pragma unroll
    for (int i = 0; i < 4; i++) v[i] = S[base + tid + i * 256];
    float mx = fmaxf(fmaxf(v[0], v[1]), fmaxf(v[2], v[3]));
    #pragma unroll
    for (int o = 16; o > 0; o >>= 1) mx = fmaxf(mx, __shfl_xor_sync(0xffffffffu, mx, o));
    __shared__ float red[8];
    if (lane == 0) red[warp] = mx;
    __syncthreads();
    float mAll = red[0];
    #pragma unroll
    for (int w = 1; w < 8; w++) mAll = fmaxf(mAll, red[w]);
    __syncthreads();

    float e[4], s = 0.f;
    #pragma unroll
    for (int i = 0; i < 4; i++) { e[i] = __expf(v[i] - mAll); s += e[i]; }
    #pragma unroll
    for (int o = 16; o > 0; o >>= 1) s += __shfl_xor_sync(0xffffffffu, s, o);
    if (lane == 0) red[warp] = s;
    __syncthreads();
    float tot = 0.f;
    #pragma unroll
    for (int w = 0; w < 8; w++) tot += red[w];
    float inv = __fdividef(1.0f, tot);
    #pragma unroll
    for (int i = 0; i < 4; i++) {
        float p = e[i] * inv;
        A[base + tid + i * 256] = p;
        if (WB) g_poolh[bfOff + base + tid + i * 256] = __float2bfloat16(p);
    }
}

// =====================================================================
// Batched bf16 mma GEMM for C_fwd / C_bwd (32 batches of 1024^3, NN).
// z<16: Cf[z] = A0h[z] @ A1h[z];  z>=16: Cb[z-16] = A1h[z-16] @ A0h[z-16].
// CTA tile 128x128x32, 8 warps (2x4), warp tile 64x32, mma m16n8k16.
// =====================================================================
__device__ __forceinline__ void mma16816(float* c, const uint32_t* a, const uint32_t* b) {
    asm volatile(
        "mma.sync.aligned.m16n8k16.row.col.f32.bf16.bf16.f32 "
        "{%0,%1,%2,%3}, {%4,%5,%6,%7}, {%8,%9}, {%0,%1,%2,%3};"
        : "+f"(c[0]), "+f"(c[1]), "+f"(c[2]), "+f"(c[3])
        : "r"(a[0]), "r"(a[1]), "r"(a[2]), "r"(a[3]), "r"(b[0]), "r"(b[1]));
}

__global__ __launch_bounds__(256) void gemm_chain_bf16() {
    int z = blockIdx.z;
    const __nv_bfloat16 *A, *B;
    float* C;
    if (z < 16) {
        A = g_poolh + OFF_A0H + (size_t)z * NN;
        B = g_poolh + OFF_A1H + (size_t)z * NN;
        C = g_pool  + OFF_CF  + (size_t)z * NN;
    } else {
        int zz = z - 16;
        A = g_poolh + OFF_A1H + (size_t)zz * NN;
        B = g_poolh + OFF_A0H + (size_t)zz * NN;
        C = g_pool  + OFF_CB  + (size_t)zz * NN;
    }
    __shared__ __nv_bfloat16 As[128][40];   // padded: conflict-free frag loads
    __shared__ __nv_bfloat16 Bt[128][40];   // B stored transposed [n][k]

    int tid = threadIdx.x, warp = tid >> 5, lane = tid & 31;
    int bm = blockIdx.y * 128, bn = blockIdx.x * 128;
    int wm = (warp >> 2) * 64, wn = (warp & 3) * 32;

    float acc[4][4][4] = {};

    for (int k0 = 0; k0 < 1024; k0 += 32) {
        #pragma unroll
        for (int i = 0; i < 8; i++) {
            int idx = i * 256 + tid;
            int r = idx >> 4, cp = idx & 15;
            *(__nv_bfloat162*)&As[r][cp * 2] =
                *(const __nv_bfloat162*)&A[(size_t)(bm + r) * 1024 + k0 + cp * 2];
        }
        #pragma unroll
        for (int i = 0; i < 8; i++) {
            int idx = i * 256 + tid;
            int n = idx & 127, kp = idx >> 7;
            __nv_bfloat162 p;
            p.x = B[(size_t)(k0 + kp * 2)     * 1024 + bn + n];
            p.y = B[(size_t)(k0 + kp * 2 + 1) * 1024 + bn + n];
            *(__nv_bfloat162*)&Bt[n][kp * 2] = p;
        }
        __syncthreads();
        #pragma unroll
        for (int ks = 0; ks < 2; ks++) {
            int kc  = ks * 16 + (lane & 3) * 2;
            int grp = lane >> 2;
            uint32_t a[4][4], b[4][2];
            #pragma unroll
            for (int mt = 0; mt < 4; mt++) {
                int r = wm + mt * 16 + grp;
                a[mt][0] = *(const uint32_t*)&As[r][kc];
                a[mt][1] = *(const uint32_t*)&As[r + 8][kc];
                a[mt][2] = *(const uint32_t*)&As[r][kc + 8];
                a[mt][3] = *(const uint32_t*)&As[r + 8][kc + 8];
            }
            #pragma unroll
            for (int nt = 0; nt < 4; nt++) {
                int n = wn + nt * 8 + grp;
                b[nt][0] = *(const uint32_t*)&Bt[n][kc];
                b[nt][1] = *(const uint32_t*)&Bt[n][kc + 8];
            }
            #pragma unroll
            for (int mt = 0; mt < 4; mt++)
                #pragma unroll
                for (int nt = 0; nt < 4; nt++)
                    mma16816(acc[mt][nt], a[mt], b[nt]);
        }
        __syncthreads();
    }
    #pragma unroll
    for (int mt = 0; mt < 4; mt++) {
        #pragma unroll
        for (int nt = 0; nt < 4; nt++) {
            int r = bm + wm + mt * 16 + (lane >> 2);
            int c = bn + wn + nt * 8 + (lane & 3) * 2;
            *(float2*)&C[(size_t)r * 1024 + c]       = make_float2(acc[mt][nt][0], acc[mt][nt][1]);
            *(float2*)&C[(size_t)(r + 8) * 1024 + c] = make_float2(acc[mt][nt][2], acc[mt][nt][3]);
        }
    }
}

// =====================================================================
// Fused: feat(6ch incl. transposes + logs) -> conv1+gelu -> conv2+sigmoid
//        -> gates -> Smix.  Smix written in-place into Cb buffer.
// grid (32 n-tiles, 32 m-tiles, 16 bh), 256 threads (32x, 8y; 4 rows each).
// =====================================================================
__global__ __launch_bounds__(256) void fuse_kernel(
    const float* __restrict__ w1, const float* __restrict__ b1,
    const float* __restrict__ w2, const float* __restrict__ b2)
{
    __shared__ float s0t[32][33], s1t[32][33];
    __shared__ float w1s[16][6], b1s[16], w2s[4][16], b2s[4];

    size_t off = (size_t)blockIdx.z * NN;
    int m0 = blockIdx.y * 32, n0 = blockIdx.x * 32;
    int tid = threadIdx.x;
    int tx = tid & 31, ty = tid >> 5;

    if (tid < 96)       ((float*)w1s)[tid]        = w1[tid];
    else if (tid < 112) b1s[tid - 96]             = b1[tid - 96];
    else if (tid < 176) ((float*)w2s)[tid - 112]  = w2[tid - 112];
    else if (tid < 180) b2s[tid - 176]            = b2[tid - 176];

    const float* S0 = g_pool + OFF_S0;
    const float* S1 = g_pool + OFF_S1;
    const float* Cf = g_pool + OFF_CF;
    float*       Cb = g_pool + OFF_CB;   // read Cb, write Smix (same index)

    #pragma unroll
    for (int r = 0; r < 4; r++) {
        int rr = ty + r * 8;
        s0t[rr][tx] = S0[off + (size_t)(n0 + rr) * 1024 + m0 + tx];
        s1t[rr][tx] = S1[off + (size_t)(n0 + rr) * 1024 + m0 + tx];
    }
    __syncthreads();

    #pragma unroll
    for (int r = 0; r < 4; r++) {
        int row = ty + r * 8;
        size_t gidx = off + (size_t)(m0 + row) * 1024 + n0 + tx;
        float s0 = S0[gidx], s1 = S1[gidx];
        float f2 = s0t[tx][row];   // S0^T
        float f3 = s1t[tx][row];   // S1^T
        float cr = __logf(Cf[gidx] + 1e-6f);
        float cl = __logf(Cb[gidx] + 1e-6f);
        float f[6] = { s0, s1, f2, f3, cr, cl };

        float g[4];
        #pragma unroll
        for (int o = 0; o < 4; o++) g[o] = b2s[o];

        #pragma unroll
        for (int oh = 0; oh < 16; oh++) {
            float a = b1s[oh];
            #pragma unroll
            for (int c = 0; c < 6; c++) a += w1s[oh][c] * f[c];
            float gx = 0.7978845608028654f * (a + 0.044715f * a * a * a);
            float hg = 0.5f * a * (1.0f + tanh_fast(gx));
            #pragma unroll
            for (int o = 0; o < 4; o++) g[o] += w2s[o][oh] * hg;
        }
        #pragma unroll
        for (int o = 0; o < 4; o++) g[o] = __fdividef(1.0f, 1.0f + __expf(-g[o]));

        float d   = fabsf(s0 - s1);
        float lse = fmaxf(s0, s1) + __logf(1.0f + __expf(-d));
        float smix = s0 + g[0] * s1 + g[1] * (lse - s0) - g[2] * (0.5f * s1) + g[3] * cr;
        Cb[gidx] = smix;
    }
}

// =====================================================================
// Combine: Y[b][tok][h*64+d] = yb[bh][tok][d] + sigmoid(cvl) * ych[bh][tok][d]
// =====================================================================
__global__ void combine_kernel(const float* __restrict__ cvl) {
    int idx = blockIdx.x * 256 + threadIdx.x;    // 0 .. 16*1024*64-1
    if (idx >= (int)(BH * ND)) return;
    int bh  = idx >> 16;
    int rr  = idx & 65535;
    int tok = rr >> 6;
    int d   = rr & 63;
    int b = bh >> 3, h = bh & 7;
    float sig = __fdividef(1.0f, 1.0f + __expf(-cvl[0]));
    float y = g_pool[OFF_YB + (size_t)idx] + sig * g_pool[OFF_YCH + (size_t)idx];
    g_pool[OFF_Y + ((size_t)(b * 1024 + tok)) * 512 + h * 64 + d] = y;
}

// =====================================================================
// Host launch sequence
// =====================================================================
extern "C" void kernel_launch(void* const* d_in, const int* in_sizes, int n_in,
                              void* d_out, int out_size)
{
    const float* x     = (const float*)d_in[0];
    const float* Wqkv0 = (const float*)d_in[1];
    const float* Wqkv1 = (const float*)d_in[2];
    const float* Wproj = (const float*)d_in[3];
    const float* c1w   = (const float*)d_in[4];
    const float* c1b   = (const float*)d_in[5];
    const float* c2w   = (const float*)d_in[6];
    const float* c2b   = (const float*)d_in[7];
    const float* cvl   = (const float*)d_in[8];
    float* out = (float*)d_out;

    // 1) qkv GEMMs: x[2048,512] @ Wqkv{0,1}[512,1536] -> scratch  (tf32 TC)
    gemm_tf32<128, 2, 4, false><<<dim3(12, 16, 1), 256>>>(x, 0, Wqkv0, 0, nullptr, OFF_SCR,
        512, 1536, 1536, 0, 0, 0, 512, 1.0f);
    gemm_tf32<128, 2, 4, false><<<dim3(12, 16, 1), 256>>>(x, 0, Wqkv1, 0, nullptr, OFF_SCR + 3145728ull,
        512, 1536, 1536, 0, 0, 0, 512, 1.0f);

    // 2) scatter into q/k/v [BH][N][DK]
    scatter_qkv<<<(2 * 2048 * 1536 + 255) / 256, 256>>>();

    // 3) S0 = q0 k0^T * 1/8 ; S1 = q1 k1^T * 1/8   (batched NT, 16; tf32 TC)
    gemm_tf32<128, 2, 4, true><<<dim3(8, 8, 16), 256>>>(nullptr, OFF_Q0, nullptr, OFF_K0, nullptr, OFF_S0,
        64, 64, 1024, (long long)ND, (long long)ND, (long long)NN, 64, 0.125f);
    gemm_tf32<128, 2, 4, true><<<dim3(8, 8, 16), 256>>>(nullptr, OFF_Q1, nullptr, OFF_K1, nullptr, OFF_S1,
        64, 64, 1024, (long long)ND, (long long)ND, (long long)NN, 64, 0.125f);

    // 4) A0 = softmax(S0) (+bf16) ; A1 = softmax(S1) (+bf16)
    softmax_rows<1><<<16384, 256>>>(OFF_S0, OFF_A0, OFF_A0H);
    softmax_rows<1><<<16384, 256>>>(OFF_S1, OFF_A1, OFF_A1H);

    // 5) C_fwd = A0@A1, C_bwd = A1@A0  (bf16 mma, fp32 accum; 32 batches)
    gemm_chain_bf16<<<dim3(8, 8, 32), 256>>>();

    // 6) fused feat/conv/gates/Smix  (Smix -> Cb buffer in place)
    fuse_kernel<<<dim3(32, 32, 16), 256>>>(c1w, c1b, c2w, c2b);

    // 7) A = softmax(Smix) -> reuse S0 buffer
    softmax_rows<0><<<16384, 256>>>(OFF_CB, OFF_S0, 0);

    // 8) tmp = A1 @ v1 ; ych = A0 @ tmp ; yb = A @ v0   (batched; tf32 TC)
    gemm_tf32<64, 4, 2, false><<<dim3(1, 8, 16), 256>>>(nullptr, OFF_A1, nullptr, OFF_V1, nullptr, OFF_TMP,
        1024, 64, 64, (long long)NN, (long long)ND, (long long)ND, 1024, 1.0f);
    gemm_tf32<64, 4, 2, false><<<dim3(1, 8, 16), 256>>>(nullptr, OFF_A0, nullptr, OFF_TMP, nullptr, OFF_YCH,
        1024, 64, 64, (long long)NN, (long long)ND, (long long)ND, 1024, 1.0f);
    gemm_tf32<64, 4, 2, false><<<dim3(1, 8, 16), 256>>>(nullptr, OFF_S0, nullptr, OFF_V0, nullptr, OFF_YB,
        1024, 64, 64, (long long)NN, (long long)ND, (long long)ND, 1024, 1.0f);

    // 9) combine into Y[2048][512]
    combine_kernel<<<(BH * ND + 255) / 256, 256>>>(cvl);

    // 10) out = Y @ Wproj  [2048,512] @ [512,512]  (tf32 TC)
    gemm_tf32<128, 2, 4, false><<<dim3(4, 16, 1), 256>>>(nullptr, OFF_Y, Wproj, 0, out, 0,
        512, 512, 512, 0, 0, 0, 512, 1.0f);

    (void)in_sizes; (void)n_in; (void)out_size;
}

// round 4
// speedup vs baseline: 1.3842x; 1.0717x over previous
#include <cuda_runtime.h>
#include <cuda_bf16.h>
#include <cstdint>

// ---------------- problem constants ----------------
#define BATCH   2
#define NSEQ    1024
#define DIMF    512
#define HEADS   8
#define DKH     64
#define BH      16              // BATCH*HEADS
#define NN      1048576ull      // NSEQ*NSEQ
#define ND      65536ull        // NSEQ*DKH
#define NN16    16777216ull     // BH*NN

// ---------------- scratch pool (static device memory; allocation-free) -----
#define OFF_Q0  0ull
#define OFF_K0  1048576ull
#define OFF_V0  2097152ull
#define OFF_Q1  3145728ull
#define OFF_K1  4194304ull
#define OFF_V1  5242880ull
#define OFF_S0  6291456ull
#define OFF_S1  (OFF_S0 + NN16)
#define OFF_A0  (OFF_S1 + NN16)
#define OFF_A1  (OFF_A0 + NN16)
#define OFF_CF  (OFF_A1 + NN16)
#define OFF_CB  (OFF_CF + NN16)
#define OFF_TMP (OFF_CB + NN16)
#define OFF_YCH (OFF_TMP + 1048576ull)
#define OFF_YB  (OFF_YCH + 1048576ull)
#define OFF_Y   (OFF_YB  + 1048576ull)
#define OFF_SCR (OFF_Y   + 1048576ull)
#define POOL_TOTAL (OFF_SCR + 6291456ull)   // 117,440,512 floats = 470 MB

#define OFF_A0H 0ull
#define OFF_A1H NN16

static __device__ float         g_pool [POOL_TOTAL];
static __device__ __nv_bfloat16 g_poolh[2ull * NN16];

// ---------------- helpers ----------------
__device__ __forceinline__ float tanh_fast(float x) {
    float y;
    asm("tanh.approx.f32 %0, %1;" : "=f"(y) : "f"(x));
    return y;
}

__device__ __forceinline__ uint32_t f2tf32(float x) {
    uint32_t u;
    asm("cvt.rna.tf32.f32 %0, %1;" : "=r"(u) : "f"(x));
    return u;
}

__device__ __forceinline__ void mma_tf32(float* c, const uint32_t* a, const uint32_t* b) {
    asm volatile(
        "mma.sync.aligned.m16n8k8.row.col.f32.tf32.tf32.f32 "
        "{%0,%1,%2,%3}, {%4,%5,%6,%7}, {%8,%9}, {%0,%1,%2,%3};"
        : "+f"(c[0]), "+f"(c[1]), "+f"(c[2]), "+f"(c[3])
        : "r"(a[0]), "r"(a[1]), "r"(a[2]), "r"(a[3]), "r"(b[0]), "r"(b[1]));
}

__device__ __forceinline__ void mma16816(float* c, const uint32_t* a, const uint32_t* b) {
    asm volatile(
        "mma.sync.aligned.m16n8k16.row.col.f32.bf16.bf16.f32 "
        "{%0,%1,%2,%3}, {%4,%5,%6,%7}, {%8,%9}, {%0,%1,%2,%3};"
        : "+f"(c[0]), "+f"(c[1]), "+f"(c[2]), "+f"(c[3])
        : "r"(a[0]), "r"(a[1]), "r"(a[2]), "r"(a[3]), "r"(b[0]), "r"(b[1]));
}

__device__ __forceinline__ void cp16(void* smem_dst, const void* gmem_src) {
    uint32_t s = (uint32_t)__cvta_generic_to_shared(smem_dst);
    asm volatile("cp.async.cg.shared.global [%0], [%1], 16;\n" :: "r"(s), "l"(gmem_src));
}
__device__ __forceinline__ void cp_commit() {
    asm volatile("cp.async.commit_group;\n");
}
template<int N>
__device__ __forceinline__ void cp_wait() {
    asm volatile("cp.async.wait_group %0;\n" :: "n"(N));
}

__device__ __forceinline__ void ldsm_x4(uint32_t* r, const void* smem) {
    uint32_t a = (uint32_t)__cvta_generic_to_shared(smem);
    asm volatile("ldmatrix.sync.aligned.m8n8.x4.shared.b16 {%0,%1,%2,%3}, [%4];\n"
        : "=r"(r[0]), "=r"(r[1]), "=r"(r[2]), "=r"(r[3]) : "r"(a));
}
__device__ __forceinline__ void ldsm_x4t(uint32_t* r, const void* smem) {
    uint32_t a = (uint32_t)__cvta_generic_to_shared(smem);
    asm volatile("ldmatrix.sync.aligned.m8n8.x4.trans.shared.b16 {%0,%1,%2,%3}, [%4];\n"
        : "=r"(r[0]), "=r"(r[1]), "=r"(r[2]), "=r"(r[3]) : "r"(a));
}

// =====================================================================
// tf32 tensor-core GEMM: C = alpha * A @ B (or A @ B^T), batched.
// CTA tile 128 x BN, BK=32, 256 threads (8 warps).
// =====================================================================
template<int BN, int WARPS_M, int WARPS_N, bool TRANSB>
__global__ __launch_bounds__(256) void gemm_tf32(
    const float* __restrict__ Aext, size_t offA,
    const float* __restrict__ Bext, size_t offB,
    float* __restrict__ Cext, size_t offC,
    int lda, int ldb, int ldc,
    long long sA, long long sB, long long sC,
    int K, float alpha)
{
    constexpr int BM = 128, BK = 32, LDS = BK + 4;     // stride 36
    constexpr int WM = BM / WARPS_M;
    constexpr int WN = BN / WARPS_N;
    constexpr int MT = WM / 16;
    constexpr int NT = WN / 8;
    constexpr int BITERS = BN / 32;

    const float* A = Aext ? Aext : (g_pool + offA);
    const float* B = Bext ? Bext : (g_pool + offB);
    float*       C = Cext ? Cext : (g_pool + offC);
    int z = blockIdx.z;
    A += (size_t)z * (size_t)sA;
    B += (size_t)z * (size_t)sB;
    C += (size_t)z * (size_t)sC;

    __shared__ uint32_t As[BM][LDS];
    __shared__ uint32_t Bs[BN][LDS];   // stored [n][k]

    int tid  = threadIdx.x;
    int warp = tid >> 5, lane = tid & 31;
    int grp  = lane >> 2, kq = lane & 3;
    int bm = blockIdx.y * BM, bn = blockIdx.x * BN;
    int wm = (warp / WARPS_N) * WM, wn = (warp % WARPS_N) * WN;

    float acc[MT][NT][4] = {};

    for (int k0 = 0; k0 < K; k0 += BK) {
        #pragma unroll
        for (int i = 0; i < 4; i++) {
            int linear = i * 256 + tid;
            int r = linear >> 3, c4 = linear & 7;
            float4 v = *(const float4*)&A[(size_t)(bm + r) * lda + k0 + c4 * 4];
            uint4 u = make_uint4(f2tf32(v.x), f2tf32(v.y), f2tf32(v.z), f2tf32(v.w));
            *(uint4*)&As[r][c4 * 4] = u;
        }
        if (TRANSB) {
            #pragma unroll
            for (int i = 0; i < BITERS; i++) {
                int linear = i * 256 + tid;
                int n = linear >> 3, c4 = linear & 7;
                float4 v = *(const float4*)&B[(size_t)(bn + n) * ldb + k0 + c4 * 4];
                uint4 u = make_uint4(f2tf32(v.x), f2tf32(v.y), f2tf32(v.z), f2tf32(v.w));
                *(uint4*)&Bs[n][c4 * 4] = u;
            }
        } else {
            #pragma unroll
            for (int i = 0; i < BITERS; i++) {
                int linear = i * 256 + tid;
                int n4 = linear % (BN / 4), k = linear / (BN / 4);
                float4 v = *(const float4*)&B[(size_t)(k0 + k) * ldb + bn + n4 * 4];
                Bs[n4 * 4 + 0][k] = f2tf32(v.x);
                Bs[n4 * 4 + 1][k] = f2tf32(v.y);
                Bs[n4 * 4 + 2][k] = f2tf32(v.z);
                Bs[n4 * 4 + 3][k] = f2tf32(v.w);
            }
        }
        __syncthreads();

        #pragma unroll
        for (int ks = 0; ks < 4; ks++) {
            int kc = ks * 8 + kq;
            uint32_t a[MT][4], b[NT][2];
            #pragma unroll
            for (int mt = 0; mt < MT; mt++) {
                int r = wm + mt * 16 + grp;
                a[mt][0] = As[r][kc];
                a[mt][1] = As[r + 8][kc];
                a[mt][2] = As[r][kc + 4];
                a[mt][3] = As[r + 8][kc + 4];
            }
            #pragma unroll
            for (int nt = 0; nt < NT; nt++) {
                int n = wn + nt * 8 + grp;
                b[nt][0] = Bs[n][kc];
                b[nt][1] = Bs[n][kc + 4];
            }
            #pragma unroll
            for (int mt = 0; mt < MT; mt++)
                #pragma unroll
                for (int nt = 0; nt < NT; nt++)
                    mma_tf32(acc[mt][nt], a[mt], b[nt]);
        }
        __syncthreads();
    }

    #pragma unroll
    for (int mt = 0; mt < MT; mt++) {
        #pragma unroll
        for (int nt = 0; nt < NT; nt++) {
            int r = bm + wm + mt * 16 + grp;
            int c = bn + wn + nt * 8 + kq * 2;
            *(float2*)&C[(size_t)r * ldc + c] =
                make_float2(alpha * acc[mt][nt][0], alpha * acc[mt][nt][1]);
            *(float2*)&C[(size_t)(r + 8) * ldc + c] =
                make_float2(alpha * acc[mt][nt][2], alpha * acc[mt][nt][3]);
        }
    }
}

// =====================================================================
// Scatter x@Wqkv result into q/k/v [BH][N][DK] layouts
// =====================================================================
__global__ void scatter_qkv() {
    int idx = blockIdx.x * 256 + threadIdx.x;   // 0 .. 2*2048*1536-1
    if (idx >= 2 * 2048 * 1536) return;
    int w   = idx / (2048 * 1536);
    int rem = idx - w * (2048 * 1536);
    int m = rem / 1536;
    int j = rem - m * 1536;
    int b = m >> 10, tok = m & 1023;
    int s = j >> 9;
    int h = (j >> 6) & 7;
    int d = j & 63;
    float val = g_pool[OFF_SCR + (size_t)idx];
    size_t baseoff;
    if (w == 0) baseoff = (s == 0) ? OFF_Q0 : (s == 1) ? OFF_K0 : OFF_V0;
    else        baseoff = (s == 0) ? OFF_Q1 : (s == 1) ? OFF_K1 : OFF_V1;
    g_pool[baseoff + ((size_t)(b * 8 + h) * NSEQ + tok) * DKH + d] = val;
}

// =====================================================================
// Row softmax over 1024 elems; optionally also write bf16 copy.
// =====================================================================
template<int WB>
__global__ __launch_bounds__(256) void softmax_rows(size_t inOff, size_t outOff, size_t bfOff)
{
    const float* S = g_pool + inOff;
    float*       A = g_pool + outOff;
    size_t base = (size_t)blockIdx.x * 1024;
    int tid = threadIdx.x;
    int warp = tid >> 5, lane = tid & 31;

    float v[4];
    #pragma unroll
    for (int i = 0; i < 4; i++) v[i] = S[base + tid + i * 256];
    float mx = fmaxf(fmaxf(v[0], v[1]), fmaxf(v[2], v[3]));
    #pragma unroll
    for (int o = 16; o > 0; o >>= 1) mx = fmaxf(mx, __shfl_xor_sync(0xffffffffu, mx, o));
    __shared__ float red[8];
    if (lane == 0) red[warp] = mx;
    __syncthreads();
    float mAll = red[0];
    #pragma unroll
    for (int w = 1; w < 8; w++) mAll = fmaxf(mAll, red[w]);
    __syncthreads();

    float e[4], s = 0.f;
    #pragma unroll
    for (int i = 0; i < 4; i++) { e[i] = __expf(v[i] - mAll); s += e[i]; }
    #pragma unroll
    for (int o = 16; o > 0; o >>= 1) s += __shfl_xor_sync(0xffffffffu, s, o);
    if (lane == 0) red[warp] = s;
    __syncthreads();
    float tot = 0.f;
    #pragma unroll
    for (int w = 0; w < 8; w++) tot += red[w];
    float inv = __fdividef(1.0f, tot);
    #pragma unroll
    for (int i = 0; i < 4; i++) {
        float p = e[i] * inv;
        A[base + tid + i * 256] = p;
        if (WB) g_poolh[bfOff + base + tid + i * 256] = __float2bfloat16(p);
    }
}

// =====================================================================
// Batched bf16 mma GEMM for C_fwd / C_bwd — v2:
// cp.async double-buffered, ldmatrix fragment loads.
// z<16: Cf[z] = A0h[z] @ A1h[z];  z>=16: Cb[z-16] = A1h[z-16] @ A0h[z-16].
// CTA tile 128x128, BK=32, 8 warps (2x4), warp tile 64x32.
// As: [buf][128][32+8]  (row-major, padded, LDSM-conflict-free)
// Bs: [buf][32][128+8]  (native [k][n], padded; consumed via LDSM.trans)
// =====================================================================
__global__ __launch_bounds__(256) void gemm_chain_bf16() {
    int z = blockIdx.z;
    const __nv_bfloat16 *A, *B;
    float* C;
    if (z < 16) {
        A = g_poolh + OFF_A0H + (size_t)z * NN;
        B = g_poolh + OFF_A1H + (size_t)z * NN;
        C = g_pool  + OFF_CF  + (size_t)z * NN;
    } else {
        int zz = z - 16;
        A = g_poolh + OFF_A1H + (size_t)zz * NN;
        B = g_poolh + OFF_A0H + (size_t)zz * NN;
        C = g_pool  + OFF_CB  + (size_t)zz * NN;
    }

    __shared__ __nv_bfloat16 As[2][128][40];   // 20,480 B
    __shared__ __nv_bfloat16 Bs[2][32][136];   // 17,408 B

    int tid = threadIdx.x, warp = tid >> 5, lane = tid & 31;
    int bm = blockIdx.y * 128, bn = blockIdx.x * 128;
    int wm = (warp >> 2) * 64, wn = (warp & 3) * 32;

    // cp.async tile loader: A 512 chunks of 16B, B 512 chunks of 16B
    auto load_tiles = [&](int k0, int buf) {
        #pragma unroll
        for (int i = 0; i < 2; i++) {
            int idx = i * 256 + tid;
            int r = idx >> 2, c16 = idx & 3;
            cp16(&As[buf][r][c16 * 8], &A[(size_t)(bm + r) * 1024 + k0 + c16 * 8]);
        }
        #pragma unroll
        for (int i = 0; i < 2; i++) {
            int idx = i * 256 + tid;
            int k = idx >> 4, c16 = idx & 15;
            cp16(&Bs[buf][k][c16 * 8], &B[(size_t)(k0 + k) * 1024 + bn + c16 * 8]);
        }
    };

    float acc[4][4][4] = {};

    load_tiles(0, 0);
    cp_commit();

    int buf = 0;
    for (int k0 = 0; k0 < 1024; k0 += 32) {
        if (k0 + 32 < 1024) load_tiles(k0 + 32, buf ^ 1);
        cp_commit();
        cp_wait<1>();
        __syncthreads();

        #pragma unroll
        for (int ks = 0; ks < 2; ks++) {
            int kb = ks * 16;
            uint32_t a[4][4], b[4][2];
            #pragma unroll
            for (int mt = 0; mt < 4; mt++)
                ldsm_x4(a[mt], &As[buf][wm + mt * 16 + (lane & 15)][kb + ((lane >> 4) << 3)]);
            #pragma unroll
            for (int p = 0; p < 2; p++) {
                uint32_t r[4];
                ldsm_x4t(r, &Bs[buf][kb + (lane & 7) + (((lane >> 3) & 1) << 3)]
                                    [wn + p * 16 + ((lane >> 4) << 3)]);
                b[2 * p][0] = r[0]; b[2 * p][1] = r[1];
                b[2 * p + 1][0] = r[2]; b[2 * p + 1][1] = r[3];
            }
            #pragma unroll
            for (int mt = 0; mt < 4; mt++)
                #pragma unroll
                for (int nt = 0; nt < 4; nt++)
                    mma16816(acc[mt][nt], a[mt], b[nt]);
        }
        __syncthreads();   // all reads of buf done before next prefetch overwrites it
        buf ^= 1;
    }

    #pragma unroll
    for (int mt = 0; mt < 4; mt++) {
        #pragma unroll
        for (int nt = 0; nt < 4; nt++) {
            int r = bm + wm + mt * 16 + (lane >> 2);
            int c = bn + wn + nt * 8 + (lane & 3) * 2;
            *(float2*)&C[(size_t)r * 1024 + c]       = make_float2(acc[mt][nt][0], acc[mt][nt][1]);
            *(float2*)&C[(size_t)(r + 8) * 1024 + c] = make_float2(acc[mt][nt][2], acc[mt][nt][3]);
        }
    }
}

// =====================================================================
// Fused: feat -> conv1+gelu -> conv2+sigmoid -> gates -> Smix (in Cb).
// =====================================================================
__global__ __launch_bounds__(256) void fuse_kernel(
    const float* __restrict__ w1, const float* __restrict__ b1,
    const float* __restrict__ w2, const float* __restrict__ b2)
{
    __shared__ float s0t[32][33], s1t[32][33];
    __shared__ float w1s[16][6], b1s[16], w2s[4][16], b2s[4];

    size_t off = (size_t)blockIdx.z * NN;
    int m0 = blockIdx.y * 32, n0 = blockIdx.x * 32;
    int tid = threadIdx.x;
    int tx = tid & 31, ty = tid >> 5;

    if (tid < 96)       ((float*)w1s)[tid]        = w1[tid];
    else if (tid < 112) b1s[tid - 96]             = b1[tid - 96];
    else if (tid < 176) ((float*)w2s)[tid - 112]  = w2[tid - 112];
    else if (tid < 180) b2s[tid - 176]            = b2[tid - 176];

    const float* S0 = g_pool + OFF_S0;
    const float* S1 = g_pool + OFF_S1;
    const float* Cf = g_pool + OFF_CF;
    float*       Cb = g_pool + OFF_CB;

    #pragma unroll
    for (int r = 0; r < 4; r++) {
        int rr = ty + r * 8;
        s0t[rr][tx] = S0[off + (size_t)(n0 + rr) * 1024 + m0 + tx];
        s1t[rr][tx] = S1[off + (size_t)(n0 + rr) * 1024 + m0 + tx];
    }
    __syncthreads();

    #pragma unroll
    for (int r = 0; r < 4; r++) {
        int row = ty + r * 8;
        size_t gidx = off + (size_t)(m0 + row) * 1024 + n0 + tx;
        float s0 = S0[gidx], s1 = S1[gidx];
        float f2 = s0t[tx][row];   // S0^T
        float f3 = s1t[tx][row];   // S1^T
        float cr = __logf(Cf[gidx] + 1e-6f);
        float cl = __logf(Cb[gidx] + 1e-6f);
        float f[6] = { s0, s1, f2, f3, cr, cl };

        float g[4];
        #pragma unroll
        for (int o = 0; o < 4; o++) g[o] = b2s[o];

        #pragma unroll
        for (int oh = 0; oh < 16; oh++) {
            float a = b1s[oh];
            #pragma unroll
            for (int c = 0; c < 6; c++) a += w1s[oh][c] * f[c];
            float gx = 0.7978845608028654f * (a + 0.044715f * a * a * a);
            float hg = 0.5f * a * (1.0f + tanh_fast(gx));
            #pragma unroll
            for (int o = 0; o < 4; o++) g[o] += w2s[o][oh] * hg;
        }
        #pragma unroll
        for (int o = 0; o < 4; o++) g[o] = __fdividef(1.0f, 1.0f + __expf(-g[o]));

        float d   = fabsf(s0 - s1);
        float lse = fmaxf(s0, s1) + __logf(1.0f + __expf(-d));
        float smix = s0 + g[0] * s1 + g[1] * (lse - s0) - g[2] * (0.5f * s1) + g[3] * cr;
        Cb[gidx] = smix;
    }
}

// =====================================================================
// Combine: Y[b][tok][h*64+d] = yb + sigmoid(cvl) * ych
// =====================================================================
__global__ void combine_kernel(const float* __restrict__ cvl) {
    int idx = blockIdx.x * 256 + threadIdx.x;
    if (idx >= (int)(BH * ND)) return;
    int bh  = idx >> 16;
    int rr  = idx & 65535;
    int tok = rr >> 6;
    int d   = rr & 63;
    int b = bh >> 3, h = bh & 7;
    float sig = __fdividef(1.0f, 1.0f + __expf(-cvl[0]));
    float y = g_pool[OFF_YB + (size_t)idx] + sig * g_pool[OFF_YCH + (size_t)idx];
    g_pool[OFF_Y + ((size_t)(b * 1024 + tok)) * 512 + h * 64 + d] = y;
}

// =====================================================================
// Host launch sequence
// =====================================================================
extern "C" void kernel_launch(void* const* d_in, const int* in_sizes, int n_in,
                              void* d_out, int out_size)
{
    const float* x     = (const float*)d_in[0];
    const float* Wqkv0 = (const float*)d_in[1];
    const float* Wqkv1 = (const float*)d_in[2];
    const float* Wproj = (const float*)d_in[3];
    const float* c1w   = (const float*)d_in[4];
    const float* c1b   = (const float*)d_in[5];
    const float* c2w   = (const float*)d_in[6];
    const float* c2b   = (const float*)d_in[7];
    const float* cvl   = (const float*)d_in[8];
    float* out = (float*)d_out;

    // 1) qkv GEMMs (tf32 TC)
    gemm_tf32<128, 2, 4, false><<<dim3(12, 16, 1), 256>>>(x, 0, Wqkv0, 0, nullptr, OFF_SCR,
        512, 1536, 1536, 0, 0, 0, 512, 1.0f);
    gemm_tf32<128, 2, 4, false><<<dim3(12, 16, 1), 256>>>(x, 0, Wqkv1, 0, nullptr, OFF_SCR + 3145728ull,
        512, 1536, 1536, 0, 0, 0, 512, 1.0f);

    // 2) scatter into q/k/v [BH][N][DK]
    scatter_qkv<<<(2 * 2048 * 1536 + 255) / 256, 256>>>();

    // 3) S0, S1 (batched NT, tf32 TC)
    gemm_tf32<128, 2, 4, true><<<dim3(8, 8, 16), 256>>>(nullptr, OFF_Q0, nullptr, OFF_K0, nullptr, OFF_S0,
        64, 64, 1024, (long long)ND, (long long)ND, (long long)NN, 64, 0.125f);
    gemm_tf32<128, 2, 4, true><<<dim3(8, 8, 16), 256>>>(nullptr, OFF_Q1, nullptr, OFF_K1, nullptr, OFF_S1,
        64, 64, 1024, (long long)ND, (long long)ND, (long long)NN, 64, 0.125f);

    // 4) softmaxes (+bf16 copies)
    softmax_rows<1><<<16384, 256>>>(OFF_S0, OFF_A0, OFF_A0H);
    softmax_rows<1><<<16384, 256>>>(OFF_S1, OFF_A1, OFF_A1H);

    // 5) C_fwd / C_bwd (bf16 mma, cp.async double-buffered)
    gemm_chain_bf16<<<dim3(8, 8, 32), 256>>>();

    // 6) fused feat/conv/gates/Smix
    fuse_kernel<<<dim3(32, 32, 16), 256>>>(c1w, c1b, c2w, c2b);

    // 7) A = softmax(Smix) -> S0 buffer
    softmax_rows<0><<<16384, 256>>>(OFF_CB, OFF_S0, 0);

    // 8) AV GEMMs (tf32 TC)
    gemm_tf32<64, 4, 2, false><<<dim3(1, 8, 16), 256>>>(nullptr, OFF_A1, nullptr, OFF_V1, nullptr, OFF_TMP,
        1024, 64, 64, (long long)NN, (long long)ND, (long long)ND, 1024, 1.0f);
    gemm_tf32<64, 4, 2, false><<<dim3(1, 8, 16), 256>>>(nullptr, OFF_A0, nullptr, OFF_TMP, nullptr, OFF_YCH,
        1024, 64, 64, (long long)NN, (long long)ND, (long long)ND, 1024, 1.0f);
    gemm_tf32<64, 4, 2, false><<<dim3(1, 8, 16), 256>>>(nullptr, OFF_S0, nullptr, OFF_V0, nullptr, OFF_YB,
        1024, 64, 64, (long long)NN, (long long)ND, (long long)ND, 1024, 1.0f);

    // 9) combine into Y
    combine_kernel<<<(BH * ND + 255) / 256, 256>>>(cvl);

    // 10) out = Y @ Wproj (tf32 TC)
    gemm_tf32<128, 2, 4, false><<<dim3(4, 16, 1), 256>>>(nullptr, OFF_Y, Wproj, 0, out, 0,
        512, 512, 512, 0, 0, 0, 512, 1.0f);

    (void)in_sizes; (void)n_in; (void)out_size;
}

// round 6
// speedup vs baseline: 1.5272x; 1.1033x over previous
#include <cuda_runtime.h>
#include <cuda_bf16.h>
#include <cstdint>

// ---------------- problem constants ----------------
#define BATCH   2
#define NSEQ    1024
#define DIMF    512
#define HEADS   8
#define DKH     64
#define BH      16              // BATCH*HEADS
#define NN      1048576ull      // NSEQ*NSEQ
#define ND      65536ull        // NSEQ*DKH
#define NN16    16777216ull     // BH*NN

// ---------------- scratch pool (static device memory; allocation-free) -----
#define OFF_Q0  0ull
#define OFF_K0  1048576ull
#define OFF_V0  2097152ull
#define OFF_Q1  3145728ull
#define OFF_K1  4194304ull
#define OFF_V1  5242880ull
#define OFF_S0  6291456ull
#define OFF_S1  (OFF_S0 + NN16)
#define OFF_A0  (OFF_S1 + NN16)
#define OFF_A1  (OFF_A0 + NN16)
#define OFF_CF  (OFF_A1 + NN16)
#define OFF_CB  (OFF_CF + NN16)
#define OFF_TMP (OFF_CB + NN16)
#define OFF_YCH (OFF_TMP + 1048576ull)
#define OFF_YB  (OFF_YCH + 1048576ull)
#define OFF_Y   (OFF_YB  + 1048576ull)
#define OFF_SCR (OFF_Y   + 1048576ull)
#define POOL_TOTAL (OFF_SCR + 6291456ull)   // 117,440,512 floats = 470 MB

#define OFF_A0H 0ull
#define OFF_A1H NN16

static __device__ float         g_pool [POOL_TOTAL];
static __device__ __nv_bfloat16 g_poolh[2ull * NN16];

// ---------------- helpers ----------------
__device__ __forceinline__ float tanh_fast(float x) {
    float y;
    asm("tanh.approx.f32 %0, %1;" : "=f"(y) : "f"(x));
    return y;
}

__device__ __forceinline__ uint32_t f2tf32(float x) {
    uint32_t u;
    asm("cvt.rna.tf32.f32 %0, %1;" : "=r"(u) : "f"(x));
    return u;
}

__device__ __forceinline__ void mma_tf32(float* c, const uint32_t* a, const uint32_t* b) {
    asm volatile(
        "mma.sync.aligned.m16n8k8.row.col.f32.tf32.tf32.f32 "
        "{%0,%1,%2,%3}, {%4,%5,%6,%7}, {%8,%9}, {%0,%1,%2,%3};"
        : "+f"(c[0]), "+f"(c[1]), "+f"(c[2]), "+f"(c[3])
        : "r"(a[0]), "r"(a[1]), "r"(a[2]), "r"(a[3]), "r"(b[0]), "r"(b[1]));
}

__device__ __forceinline__ void mma16816(float* c, const uint32_t* a, const uint32_t* b) {
    asm volatile(
        "mma.sync.aligned.m16n8k16.row.col.f32.bf16.bf16.f32 "
        "{%0,%1,%2,%3}, {%4,%5,%6,%7}, {%8,%9}, {%0,%1,%2,%3};"
        : "+f"(c[0]), "+f"(c[1]), "+f"(c[2]), "+f"(c[3])
        : "r"(a[0]), "r"(a[1]), "r"(a[2]), "r"(a[3]), "r"(b[0]), "r"(b[1]));
}

__device__ __forceinline__ void cp16(void* smem_dst, const void* gmem_src) {
    uint32_t s = (uint32_t)__cvta_generic_to_shared(smem_dst);
    asm volatile("cp.async.cg.shared.global [%0], [%1], 16;\n" :: "r"(s), "l"(gmem_src));
}
__device__ __forceinline__ void cp_commit() {
    asm volatile("cp.async.commit_group;\n");
}
template<int N>
__device__ __forceinline__ void cp_wait() {
    asm volatile("cp.async.wait_group %0;\n" :: "n"(N));
}

__device__ __forceinline__ void ldsm_x4(uint32_t* r, const void* smem) {
    uint32_t a = (uint32_t)__cvta_generic_to_shared(smem);
    asm volatile("ldmatrix.sync.aligned.m8n8.x4.shared.b16 {%0,%1,%2,%3}, [%4];\n"
        : "=r"(r[0]), "=r"(r[1]), "=r"(r[2]), "=r"(r[3]) : "r"(a));
}
__device__ __forceinline__ void ldsm_x4t(uint32_t* r, const void* smem) {
    uint32_t a = (uint32_t)__cvta_generic_to_shared(smem);
    asm volatile("ldmatrix.sync.aligned.m8n8.x4.trans.shared.b16 {%0,%1,%2,%3}, [%4];\n"
        : "=r"(r[0]), "=r"(r[1]), "=r"(r[2]), "=r"(r[3]) : "r"(a));
}

// =====================================================================
// tf32 tensor-core GEMM: C = alpha * A @ B (or A @ B^T), batched.
// DUAL=1: z<16 -> yb = A(Smix-softmax)@v0 ; z>=16 -> tmp = A1@v1
// =====================================================================
template<int BN, int WARPS_M, int WARPS_N, bool TRANSB, int DUAL>
__global__ __launch_bounds__(256) void gemm_tf32(
    const float* __restrict__ Aext, size_t offA,
    const float* __restrict__ Bext, size_t offB,
    float* __restrict__ Cext, size_t offC,
    int lda, int ldb, int ldc,
    long long sA, long long sB, long long sC,
    int K, float alpha)
{
    constexpr int BM = 128, BK = 32, LDS = BK + 4;     // stride 36
    constexpr int WM = BM / WARPS_M;
    constexpr int WN = BN / WARPS_N;
    constexpr int MT = WM / 16;
    constexpr int NT = WN / 8;
    constexpr int BITERS = BN / 32;

    const float* A;
    const float* B;
    float*       C;
    int z = blockIdx.z;
    if (DUAL) {
        if (z < 16) {
            A = g_pool + OFF_S0 + (size_t)z * NN;     // softmax(Smix)
            B = g_pool + OFF_V0 + (size_t)z * ND;
            C = g_pool + OFF_YB + (size_t)z * ND;
        } else {
            A = g_pool + OFF_A1 + (size_t)(z - 16) * NN;
            B = g_pool + OFF_V1 + (size_t)(z - 16) * ND;
            C = g_pool + OFF_TMP + (size_t)(z - 16) * ND;
        }
    } else {
        A = (Aext ? Aext : (g_pool + offA)) + (size_t)z * (size_t)sA;
        B = (Bext ? Bext : (g_pool + offB)) + (size_t)z * (size_t)sB;
        C = (Cext ? Cext : (g_pool + offC)) + (size_t)z * (size_t)sC;
    }

    __shared__ uint32_t As[BM][LDS];
    __shared__ uint32_t Bs[BN][LDS];   // stored [n][k]

    int tid  = threadIdx.x;
    int warp = tid >> 5, lane = tid & 31;
    int grp  = lane >> 2, kq = lane & 3;
    int bm = blockIdx.y * BM, bn = blockIdx.x * BN;
    int wm = (warp / WARPS_N) * WM, wn = (warp % WARPS_N) * WN;

    float acc[MT][NT][4] = {};

    for (int k0 = 0; k0 < K; k0 += BK) {
        #pragma unroll
        for (int i = 0; i < 4; i++) {
            int linear = i * 256 + tid;
            int r = linear >> 3, c4 = linear & 7;
            float4 v = *(const float4*)&A[(size_t)(bm + r) * lda + k0 + c4 * 4];
            uint4 u = make_uint4(f2tf32(v.x), f2tf32(v.y), f2tf32(v.z), f2tf32(v.w));
            *(uint4*)&As[r][c4 * 4] = u;
        }
        if (TRANSB) {
            #pragma unroll
            for (int i = 0; i < BITERS; i++) {
                int linear = i * 256 + tid;
                int n = linear >> 3, c4 = linear & 7;
                float4 v = *(const float4*)&B[(size_t)(bn + n) * ldb + k0 + c4 * 4];
                uint4 u = make_uint4(f2tf32(v.x), f2tf32(v.y), f2tf32(v.z), f2tf32(v.w));
                *(uint4*)&Bs[n][c4 * 4] = u;
            }
        } else {
            #pragma unroll
            for (int i = 0; i < BITERS; i++) {
                int linear = i * 256 + tid;
                int n4 = linear % (BN / 4), k = linear / (BN / 4);
                float4 v = *(const float4*)&B[(size_t)(k0 + k) * ldb + bn + n4 * 4];
                Bs[n4 * 4 + 0][k] = f2tf32(v.x);
                Bs[n4 * 4 + 1][k] = f2tf32(v.y);
                Bs[n4 * 4 + 2][k] = f2tf32(v.z);
                Bs[n4 * 4 + 3][k] = f2tf32(v.w);
            }
        }
        __syncthreads();

        #pragma unroll
        for (int ks = 0; ks < 4; ks++) {
            int kc = ks * 8 + kq;
            uint32_t a[MT][4], b[NT][2];
            #pragma unroll
            for (int mt = 0; mt < MT; mt++) {
                int r = wm + mt * 16 + grp;
                a[mt][0] = As[r][kc];
                a[mt][1] = As[r + 8][kc];
                a[mt][2] = As[r][kc + 4];
                a[mt][3] = As[r + 8][kc + 4];
            }
            #pragma unroll
            for (int nt = 0; nt < NT; nt++) {
                int n = wn + nt * 8 + grp;
                b[nt][0] = Bs[n][kc];
                b[nt][1] = Bs[n][kc + 4];
            }
            #pragma unroll
            for (int mt = 0; mt < MT; mt++)
                #pragma unroll
                for (int nt = 0; nt < NT; nt++)
                    mma_tf32(acc[mt][nt], a[mt], b[nt]);
        }
        __syncthreads();
    }

    #pragma unroll
    for (int mt = 0; mt < MT; mt++) {
        #pragma unroll
        for (int nt = 0; nt < NT; nt++) {
            int r = bm + wm + mt * 16 + grp;
            int c = bn + wn + nt * 8 + kq * 2;
            *(float2*)&C[(size_t)r * ldc + c] =
                make_float2(alpha * acc[mt][nt][0], alpha * acc[mt][nt][1]);
            *(float2*)&C[(size_t)(r + 8) * ldc + c] =
                make_float2(alpha * acc[mt][nt][2], alpha * acc[mt][nt][3]);
        }
    }
}

// =====================================================================
// Scatter x@Wqkv result into q/k/v [BH][N][DK] layouts
// =====================================================================
__global__ void scatter_qkv() {
    int idx = blockIdx.x * 256 + threadIdx.x;   // 0 .. 2*2048*1536-1
    if (idx >= 2 * 2048 * 1536) return;
    int w   = idx / (2048 * 1536);
    int rem = idx - w * (2048 * 1536);
    int m = rem / 1536;
    int j = rem - m * 1536;
    int b = m >> 10, tok = m & 1023;
    int s = j >> 9;
    int h = (j >> 6) & 7;
    int d = j & 63;
    float val = g_pool[OFF_SCR + (size_t)idx];
    size_t baseoff;
    if (w == 0) baseoff = (s == 0) ? OFF_Q0 : (s == 1) ? OFF_K0 : OFF_V0;
    else        baseoff = (s == 0) ? OFF_Q1 : (s == 1) ? OFF_K1 : OFF_V1;
    g_pool[baseoff + ((size_t)(b * 8 + h) * NSEQ + tok) * DKH + d] = val;
}

// =====================================================================
// Row softmax over 1024 elems; optionally also write bf16 copy.
// =====================================================================
template<int WB>
__global__ __launch_bounds__(256) void softmax_rows(size_t inOff, size_t outOff, size_t bfOff)
{
    const float* S = g_pool + inOff;
    float*       A = g_pool + outOff;
    size_t base = (size_t)blockIdx.x * 1024;
    int tid = threadIdx.x;
    int warp = tid >> 5, lane = tid & 31;

    float v[4];
    #pragma unroll
    for (int i = 0; i < 4; i++) v[i] = S[base + tid + i * 256];
    float mx = fmaxf(fmaxf(v[0], v[1]), fmaxf(v[2], v[3]));
    #pragma unroll
    for (int o = 16; o > 0; o >>= 1) mx = fmaxf(mx, __shfl_xor_sync(0xffffffffu, mx, o));
    __shared__ float red[8];
    if (lane == 0) red[warp] = mx;
    __syncthreads();
    float mAll = red[0];
    #pragma unroll
    for (int w = 1; w < 8; w++) mAll = fmaxf(mAll, red[w]);
    __syncthreads();

    float e[4], s = 0.f;
    #pragma unroll
    for (int i = 0; i < 4; i++) { e[i] = __expf(v[i] - mAll); s += e[i]; }
    #pragma unroll
    for (int o = 16; o > 0; o >>= 1) s += __shfl_xor_sync(0xffffffffu, s, o);
    if (lane == 0) red[warp] = s;
    __syncthreads();
    float tot = 0.f;
    #pragma unroll
    for (int w = 0; w < 8; w++) tot += red[w];
    float inv = __fdividef(1.0f, tot);
    #pragma unroll
    for (int i = 0; i < 4; i++) {
        float p = e[i] * inv;
        A[base + tid + i * 256] = p;
        if (WB) g_poolh[bfOff + base + tid + i * 256] = __float2bfloat16(p);
    }
}

// =====================================================================
// Chain GEMM v3: bf16 mma.sync, 3-stage cp.async pipeline, BK=64.
// z<16: Cf[z] = A0h[z] @ A1h[z];  z>=16: Cb[z-16] = A1h[z-16] @ A0h[z-16].
// CTA 128x128, 8 warps (2x4), warp tile 64x32. One __syncthreads per chunk.
// Dynamic smem: 3 stages x (As 128x72 + Bs 64x136) bf16 = 107,520 B.
// =====================================================================
#define CH_ASTR 72
#define CH_BSTR 136
#define CH_AELEM (128 * CH_ASTR)            // 9216
#define CH_BELEM (64 * CH_BSTR)             // 8704
#define CH_STAGE (CH_AELEM + CH_BELEM)      // 17920 elems
#define CH_SMEM  (3 * CH_STAGE * 2)         // 107,520 bytes

__global__ __launch_bounds__(256) void gemm_chain_v3() {
    extern __shared__ __nv_bfloat16 sm[];

    int z = blockIdx.z;
    const __nv_bfloat16 *A, *B;
    float* C;
    if (z < 16) {
        A = g_poolh + OFF_A0H + (size_t)z * NN;
        B = g_poolh + OFF_A1H + (size_t)z * NN;
        C = g_pool  + OFF_CF  + (size_t)z * NN;
    } else {
        int zz = z - 16;
        A = g_poolh + OFF_A1H + (size_t)zz * NN;
        B = g_poolh + OFF_A0H + (size_t)zz * NN;
        C = g_pool  + OFF_CB  + (size_t)zz * NN;
    }

    int tid = threadIdx.x, warp = tid >> 5, lane = tid & 31;
    int bm = blockIdx.y * 128, bn = blockIdx.x * 128;
    int wm = (warp >> 2) * 64, wn = (warp & 3) * 32;

    // stage s: As at sm + s*CH_STAGE, Bs at sm + s*CH_STAGE + CH_AELEM
    auto load_stage = [&](int chunk, int s) {
        __nv_bfloat16* Ab = sm + s * CH_STAGE;
        __nv_bfloat16* Bb = Ab + CH_AELEM;
        int k0 = chunk * 64;
        #pragma unroll
        for (int i = 0; i < 4; i++) {
            int idx = i * 256 + tid;
            int r = idx >> 3, c16 = idx & 7;        // A: 128 rows x 8 chunks
            cp16(Ab + r * CH_ASTR + c16 * 8,
                 A + (size_t)(bm + r) * 1024 + k0 + c16 * 8);
        }
        #pragma unroll
        for (int i = 0; i < 4; i++) {
            int idx = i * 256 + tid;
            int k = idx >> 4, c16 = idx & 15;       // B: 64 k-rows x 16 chunks
            cp16(Bb + k * CH_BSTR + c16 * 8,
                 B + (size_t)(k0 + k) * 1024 + bn + c16 * 8);
        }
    };

    float acc[4][4][4] = {};

    load_stage(0, 0); cp_commit();
    load_stage(1, 1); cp_commit();

    for (int c = 0; c < 16; c++) {
        cp_wait<1>();          // stage c%3 complete (in-order retirement)
        __syncthreads();       // visibility + all warps done with stage (c-1)%3

        if (c + 2 < 16) load_stage(c + 2, (c + 2) % 3);
        cp_commit();           // unconditional: keeps group accounting uniform

        const __nv_bfloat16* Ab = sm + (c % 3) * CH_STAGE;
        const __nv_bfloat16* Bb = Ab + CH_AELEM;

        #pragma unroll
        for (int ks = 0; ks < 4; ks++) {
            int kb = ks * 16;
            uint32_t a[4][4], b[4][2];
            #pragma unroll
            for (int mt = 0; mt < 4; mt++)
                ldsm_x4(a[mt], Ab + (wm + mt * 16 + (lane & 15)) * CH_ASTR
                                  + kb + ((lane >> 4) << 3));
            #pragma unroll
            for (int p = 0; p < 2; p++) {
                uint32_t r[4];
                ldsm_x4t(r, Bb + (kb + (lane & 7) + (((lane >> 3) & 1) << 3)) * CH_BSTR
                               + wn + p * 16 + ((lane >> 4) << 3));
                b[2 * p][0] = r[0]; b[2 * p][1] = r[1];
                b[2 * p + 1][0] = r[2]; b[2 * p + 1][1] = r[3];
            }
            #pragma unroll
            for (int mt = 0; mt < 4; mt++)
                #pragma unroll
                for (int nt = 0; nt < 4; nt++)
                    mma16816(acc[mt][nt], a[mt], b[nt]);
        }
    }

    #pragma unroll
    for (int mt = 0; mt < 4; mt++) {
        #pragma unroll
        for (int nt = 0; nt < 4; nt++) {
            int r = bm + wm + mt * 16 + (lane >> 2);
            int cc = bn + wn + nt * 8 + (lane & 3) * 2;
            *(float2*)&C[(size_t)r * 1024 + cc]       = make_float2(acc[mt][nt][0], acc[mt][nt][1]);
            *(float2*)&C[(size_t)(r + 8) * 1024 + cc] = make_float2(acc[mt][nt][2], acc[mt][nt][3]);
        }
    }
}

// =====================================================================
// Fused: feat -> conv1+gelu -> conv2+sigmoid -> gates -> Smix (in Cb).
// =====================================================================
__global__ __launch_bounds__(256) void fuse_kernel(
    const float* __restrict__ w1, const float* __restrict__ b1,
    const float* __restrict__ w2, const float* __restrict__ b2)
{
    __shared__ float s0t[32][33], s1t[32][33];
    __shared__ float w1s[16][6], b1s[16], w2s[4][16], b2s[4];

    size_t off = (size_t)blockIdx.z * NN;
    int m0 = blockIdx.y * 32, n0 = blockIdx.x * 32;
    int tid = threadIdx.x;
    int tx = tid & 31, ty = tid >> 5;

    if (tid < 96)       ((float*)w1s)[tid]        = w1[tid];
    else if (tid < 112) b1s[tid - 96]             = b1[tid - 96];
    else if (tid < 176) ((float*)w2s)[tid - 112]  = w2[tid - 112];
    else if (tid < 180) b2s[tid - 176]            = b2[tid - 176];

    const float* S0 = g_pool + OFF_S0;
    const float* S1 = g_pool + OFF_S1;
    const float* Cf = g_pool + OFF_CF;
    float*       Cb = g_pool + OFF_CB;

    #pragma unroll
    for (int r = 0; r < 4; r++) {
        int rr = ty + r * 8;
        s0t[rr][tx] = S0[off + (size_t)(n0 + rr) * 1024 + m0 + tx];
        s1t[rr][tx] = S1[off + (size_t)(n0 + rr) * 1024 + m0 + tx];
    }
    __syncthreads();

    #pragma unroll
    for (int r = 0; r < 4; r++) {
        int row = ty + r * 8;
        size_t gidx = off + (size_t)(m0 + row) * 1024 + n0 + tx;
        float s0 = S0[gidx], s1 = S1[gidx];
        float f2 = s0t[tx][row];   // S0^T
        float f3 = s1t[tx][row];   // S1^T
        float cr = __logf(Cf[gidx] + 1e-6f);
        float cl = __logf(Cb[gidx] + 1e-6f);
        float f[6] = { s0, s1, f2, f3, cr, cl };

        float g[4];
        #pragma unroll
        for (int o = 0; o < 4; o++) g[o] = b2s[o];

        #pragma unroll
        for (int oh = 0; oh < 16; oh++) {
            float a = b1s[oh];
            #pragma unroll
            for (int c = 0; c < 6; c++) a += w1s[oh][c] * f[c];
            float gx = 0.7978845608028654f * (a + 0.044715f * a * a * a);
            float hg = 0.5f * a * (1.0f + tanh_fast(gx));
            #pragma unroll
            for (int o = 0; o < 4; o++) g[o] += w2s[o][oh] * hg;
        }
        #pragma unroll
        for (int o = 0; o < 4; o++) g[o] = __fdividef(1.0f, 1.0f + __expf(-g[o]));

        float d   = fabsf(s0 - s1);
        float lse = fmaxf(s0, s1) + __logf(1.0f + __expf(-d));
        float smix = s0 + g[0] * s1 + g[1] * (lse - s0) - g[2] * (0.5f * s1) + g[3] * cr;
        Cb[gidx] = smix;
    }
}

// =====================================================================
// Combine: Y[b][tok][h*64+d] = yb + sigmoid(cvl) * ych
// =====================================================================
__global__ void combine_kernel(const float* __restrict__ cvl) {
    int idx = blockIdx.x * 256 + threadIdx.x;
    if (idx >= (int)(BH * ND)) return;
    int bh  = idx >> 16;
    int rr  = idx & 65535;
    int tok = rr >> 6;
    int d   = rr & 63;
    int b = bh >> 3, h = bh & 7;
    float sig = __fdividef(1.0f, 1.0f + __expf(-cvl[0]));
    float y = g_pool[OFF_YB + (size_t)idx] + sig * g_pool[OFF_YCH + (size_t)idx];
    g_pool[OFF_Y + ((size_t)(b * 1024 + tok)) * 512 + h * 64 + d] = y;
}

// =====================================================================
// Host launch sequence
// =====================================================================
extern "C" void kernel_launch(void* const* d_in, const int* in_sizes, int n_in,
                              void* d_out, int out_size)
{
    const float* x     = (const float*)d_in[0];
    const float* Wqkv0 = (const float*)d_in[1];
    const float* Wqkv1 = (const float*)d_in[2];
    const float* Wproj = (const float*)d_in[3];
    const float* c1w   = (const float*)d_in[4];
    const float* c1b   = (const float*)d_in[5];
    const float* c2w   = (const float*)d_in[6];
    const float* c2b   = (const float*)d_in[7];
    const float* cvl   = (const float*)d_in[8];
    float* out = (float*)d_out;

    // allow >48KB dynamic smem for the chain kernel (idempotent)
    cudaFuncSetAttribute(gemm_chain_v3,
                         cudaFuncAttributeMaxDynamicSharedMemorySize, CH_SMEM);

    // 1) qkv GEMMs (tf32 TC)
    gemm_tf32<128, 2, 4, false, 0><<<dim3(12, 16, 1), 256>>>(x, 0, Wqkv0, 0, nullptr, OFF_SCR,
        512, 1536, 1536, 0, 0, 0, 512, 1.0f);
    gemm_tf32<128, 2, 4, false, 0><<<dim3(12, 16, 1), 256>>>(x, 0, Wqkv1, 0, nullptr, OFF_SCR + 3145728ull,
        512, 1536, 1536, 0, 0, 0, 512, 1.0f);

    // 2) scatter into q/k/v [BH][N][DK]
    scatter_qkv<<<(2 * 2048 * 1536 + 255) / 256, 256>>>();

    // 3) S0, S1 (batched NT, tf32 TC)
    gemm_tf32<128, 2, 4, true, 0><<<dim3(8, 8, 16), 256>>>(nullptr, OFF_Q0, nullptr, OFF_K0, nullptr, OFF_S0,
        64, 64, 1024, (long long)ND, (long long)ND, (long long)NN, 64, 0.125f);
    gemm_tf32<128, 2, 4, true, 0><<<dim3(8, 8, 16), 256>>>(nullptr, OFF_Q1, nullptr, OFF_K1, nullptr, OFF_S1,
        64, 64, 1024, (long long)ND, (long long)ND, (long long)NN, 64, 0.125f);

    // 4) softmaxes (+bf16 copies)
    softmax_rows<1><<<16384, 256>>>(OFF_S0, OFF_A0, OFF_A0H);
    softmax_rows<1><<<16384, 256>>>(OFF_S1, OFF_A1, OFF_A1H);

    // 5) C_fwd / C_bwd (bf16 mma, 3-stage cp.async pipeline)
    gemm_chain_v3<<<dim3(8, 8, 32), 256, CH_SMEM>>>();

    // 6) fused feat/conv/gates/Smix
    fuse_kernel<<<dim3(32, 32, 16), 256>>>(c1w, c1b, c2w, c2b);

    // 7) A = softmax(Smix) -> S0 buffer
    softmax_rows<0><<<16384, 256>>>(OFF_CB, OFF_S0, 0);

    // 8) yb = A @ v0 and tmp = A1 @ v1 in ONE launch (z=32, independent)
    gemm_tf32<64, 4, 2, false, 1><<<dim3(1, 8, 32), 256>>>(nullptr, 0, nullptr, 0, nullptr, 0,
        1024, 64, 64, 0, 0, 0, 1024, 1.0f);

    // 9) ych = A0 @ tmp
    gemm_tf32<64, 4, 2, false, 0><<<dim3(1, 8, 16), 256>>>(nullptr, OFF_A0, nullptr, OFF_TMP, nullptr, OFF_YCH,
        1024, 64, 64, (long long)NN, (long long)ND, (long long)ND, 1024, 1.0f);

    // 10) combine into Y
    combine_kernel<<<(BH * ND + 255) / 256, 256>>>(cvl);

    // 11) out = Y @ Wproj (tf32 TC)
    gemm_tf32<128, 2, 4, false, 0><<<dim3(4, 16, 1), 256>>>(nullptr, OFF_Y, Wproj, 0, out, 0,
        512, 512, 512, 0, 0, 0, 512, 1.0f);

    (void)in_sizes; (void)n_in; (void)out_size;
}